// round 16
// baseline (speedup 1.0000x reference)
#include <cuda_runtime.h>

#define B_  4
#define C_  64
#define K_  32
#define N_  131072           // D*H*W
#define TN  128              // n-tile per block
#define XS  132              // X tile row stride (words; 528B = 16B-aligned)
#define LS  132              // L/A tile row stride
#define CWS2 68              // duplicated codeword row stride (floats; 272B)
#define E_ELEMS (B_*K_*C_)   // 8192

__device__ float g_asum[B_*K_];

typedef unsigned long long u64;

__device__ __forceinline__ u64 ffma2(u64 a, u64 b, u64 c) {
    u64 d; asm("fma.rn.f32x2 %0, %1, %2, %3;" : "=l"(d) : "l"(a), "l"(b), "l"(c));
    return d;
}
__device__ __forceinline__ u64 fadd2(u64 a, u64 b) {
    u64 d; asm("add.rn.f32x2 %0, %1, %2;" : "=l"(d) : "l"(a), "l"(b));
    return d;
}
__device__ __forceinline__ u64 pack2(float lo, float hi) {
    u64 d; asm("mov.b64 %0, {%1, %2};" : "=l"(d) : "f"(lo), "f"(hi));
    return d;
}
__device__ __forceinline__ float2 unpack2(u64 v) {
    float2 r; asm("mov.b64 {%0, %1}, %2;" : "=f"(r.x), "=f"(r.y) : "l"(v));
    return r;
}

// ---------------------------------------------------------------------------
__global__ void enc_init(float* __restrict__ out) {
    int i = blockIdx.x * 256 + threadIdx.x;
    if (i < E_ELEMS) out[i] = 0.0f;
    if (i < B_*K_)   g_asum[i] = 0.0f;
}

// ---------------------------------------------------------------------------
// One block = one (b, 128-n) tile. Grid = 4 * 1024 = 4096 blocks, 128 threads.
// ---------------------------------------------------------------------------
__global__ __launch_bounds__(128, 3) void enc_main(
    const float* __restrict__ X,    // (B, C, N)
    const float* __restrict__ cwg,  // (K, C)
    const float* __restrict__ sclg, // (K,)
    float* __restrict__ out)        // [E | coefA]
{
    extern __shared__ float sm[];
    float* Xs  = sm;                  // 64*132  X tile, [c][n] linear
    float* Lb  = Xs + 64*XS;          // 32*132  logits -> A, [k][n] linear
    float* cw2 = Lb + 32*LS;          // 64*68   duplicated pairs, split-quad layout
    float* x2s = cw2 + 64*CWS2;       // 128
    float* scl = x2s + 128;           // 32
    float* c4  = scl + 32;            // 32*4  (scl, -2*scl, scl*c2, 0)

    const int tid = threadIdx.x;
    const int b   = blockIdx.x >> 10;          // /1024
    const int n0  = (blockIdx.x & 1023) << 7;  // *128

    // ---- stage X tile (vectorized, coalesced, linear layout) ----
    const float* Xb = X + (size_t)b * C_ * N_ + n0;
    #pragma unroll
    for (int i = 0; i < 16; ++i) {
        int f = i * 128 + tid;
        int c = f >> 5, q = f & 31;            // 32 float4 per 128-n row
        float4 v = *(const float4*)(Xb + (size_t)c * N_ + q * 4);
        *(float4*)(Xs + c * XS + q * 4) = v;
    }
    // ---- stage codewords duplicated {w,w}, split-quad layout:
    //      thread-quad l = k>>2 owns float offsets [4l..4l+3] (k%4 in 0,1)
    //      and [32+4l..32+4l+3] (k%4 in 2,3), within a 68-float row per c.
    #pragma unroll
    for (int i = 0; i < 16; ++i) {
        int f = i * 128 + tid;        // f = k*64 + c
        int k = f >> 6, c = f & 63;
        int l = k >> 2, r = k & 3;
        int off = c * CWS2 + ((r < 2) ? (4*l + 2*r) : (32 + 4*l + 2*(r-2)));
        float w = cwg[f];
        *(u64*)(cw2 + off) = pack2(w, w);
    }
    if (tid < K_) scl[tid] = sclg[tid];
    __syncthreads();

    if (tid < K_) {
        float s = 0.f;
        #pragma unroll
        for (int c = 0; c < C_; ++c) { float w = cwg[tid*C_ + c]; s = fmaf(w, w, s); }
        float sc = scl[tid];
        float4 v; v.x = sc; v.y = -2.f * sc; v.z = sc * s; v.w = 0.f;
        *(float4*)(c4 + tid * 4) = v;
    }

    // ---- Phase 1: logits GEMM (dots only), 4k x 8n per thread, n-paired ----
    const int k0 = (tid & 7) * 4;
    const int nt = (tid >> 3) * 8;    // 0..120
    const int wq = (tid & 7) * 4;     // first-quad float offset = 4*l, l=tid&7
    u64 acc[4][4];                    // [npair][k]
    u64 x2a[4];
    #pragma unroll
    for (int i = 0; i < 4; ++i) {
        x2a[i] = 0ull;
        #pragma unroll
        for (int j = 0; j < 4; ++j) acc[i][j] = 0ull;
    }

    #pragma unroll 8
    for (int c = 0; c < 64; ++c) {
        ulonglong2 xa = *(const ulonglong2*)(Xs + c * XS + nt);
        ulonglong2 xb = *(const ulonglong2*)(Xs + c * XS + nt + 4);
        const float* wr = cw2 + c * CWS2;
        ulonglong2 wab = *(const ulonglong2*)(wr + wq);        // {w0,w0},{w1,w1}
        ulonglong2 wcd = *(const ulonglong2*)(wr + 32 + wq);   // {w2,w2},{w3,w3}
        acc[0][0] = ffma2(xa.x, wab.x, acc[0][0]);
        acc[0][1] = ffma2(xa.x, wab.y, acc[0][1]);
        acc[0][2] = ffma2(xa.x, wcd.x, acc[0][2]);
        acc[0][3] = ffma2(xa.x, wcd.y, acc[0][3]);
        acc[1][0] = ffma2(xa.y, wab.x, acc[1][0]);
        acc[1][1] = ffma2(xa.y, wab.y, acc[1][1]);
        acc[1][2] = ffma2(xa.y, wcd.x, acc[1][2]);
        acc[1][3] = ffma2(xa.y, wcd.y, acc[1][3]);
        acc[2][0] = ffma2(xb.x, wab.x, acc[2][0]);
        acc[2][1] = ffma2(xb.x, wab.y, acc[2][1]);
        acc[2][2] = ffma2(xb.x, wcd.x, acc[2][2]);
        acc[2][3] = ffma2(xb.x, wcd.y, acc[2][3]);
        acc[3][0] = ffma2(xb.y, wab.x, acc[3][0]);
        acc[3][1] = ffma2(xb.y, wab.y, acc[3][1]);
        acc[3][2] = ffma2(xb.y, wcd.x, acc[3][2]);
        acc[3][3] = ffma2(xb.y, wcd.y, acc[3][3]);
        x2a[0] = ffma2(xa.x, xa.x, x2a[0]);
        x2a[1] = ffma2(xa.y, xa.y, x2a[1]);
        x2a[2] = ffma2(xb.x, xb.x, x2a[2]);
        x2a[3] = ffma2(xb.y, xb.y, x2a[3]);
    }
    #pragma unroll
    for (int j = 0; j < 4; ++j)
        #pragma unroll
        for (int i = 0; i < 4; ++i)
            *(u64*)(Lb + (k0 + j) * LS + nt + 2*i) = acc[i][j];
    if ((tid & 7) == 0) {
        #pragma unroll
        for (int i = 0; i < 4; ++i) *(u64*)(x2s + nt + 2*i) = x2a[i];
    }
    __syncthreads();

    // ---- Softmax per n = tid (0..127), write coefA + A (in place) ----
    {
        float x2 = x2s[tid];
        float lg[K_];
        float mx = -1e30f;
        #pragma unroll
        for (int k = 0; k < K_; ++k) {
            float4 cc = *(const float4*)(c4 + k * 4);
            float d = Lb[k * LS + tid];
            float l = fmaf(cc.y, d, fmaf(cc.x, x2, cc.z));
            lg[k] = l;
            mx = fmaxf(mx, l);
        }
        float s = 0.f;
        #pragma unroll
        for (int k = 0; k < K_; ++k) { float e = __expf(lg[k] - mx); lg[k] = e; s += e; }
        float inv = __fdividef(1.f, s);
        float* coefA = out + E_ELEMS + (size_t)b * K_ * N_ + n0 + tid;
        #pragma unroll
        for (int k = 0; k < K_; ++k) {
            float a = lg[k] * inv;
            coefA[(size_t)k * N_] = a;     // coalesced per k
            Lb[k * LS + tid] = a;          // same words this thread read -> safe
        }
    }
    __syncthreads();

    // ---- Phase 2: A^T X, 4k x 4c per thread, c interleaved (c = cg + 16*cj),
    //      128 n, LINEAR addressing (bank = 4*cg mod 32, conflict-free) ----
    {
        const int kg  = tid >> 4;            // 0..7 -> k rows 4kg..4kg+3
        const int cg  = tid & 15;            // c cols: cg, cg+16, cg+32, cg+48
        const int k0b = kg * 4;

        const float* Ar = Lb + k0b * LS;
        const float* Xc = Xs + cg  * XS;

        u64 e[4][4];                         // [k][cj]
        u64 sa[4];
        #pragma unroll
        for (int j = 0; j < 4; ++j) {
            sa[j] = 0ull;
            #pragma unroll
            for (int cj = 0; cj < 4; ++cj) e[j][cj] = 0ull;
        }

        #pragma unroll 2
        for (int n = 0; n < TN; n += 4) {
            ulonglong2 x0 = *(const ulonglong2*)(Xc +  0 * XS + n);
            ulonglong2 x1 = *(const ulonglong2*)(Xc + 16 * XS + n);
            ulonglong2 x2v = *(const ulonglong2*)(Xc + 32 * XS + n);
            ulonglong2 x3 = *(const ulonglong2*)(Xc + 48 * XS + n);
            ulonglong2 a0 = *(const ulonglong2*)(Ar + 0 * LS + n);
            ulonglong2 a1 = *(const ulonglong2*)(Ar + 1 * LS + n);
            ulonglong2 a2 = *(const ulonglong2*)(Ar + 2 * LS + n);
            ulonglong2 a3 = *(const ulonglong2*)(Ar + 3 * LS + n);

            e[0][0] = ffma2(a0.x, x0.x,  e[0][0]); e[0][0] = ffma2(a0.y, x0.y,  e[0][0]);
            e[0][1] = ffma2(a0.x, x1.x,  e[0][1]); e[0][1] = ffma2(a0.y, x1.y,  e[0][1]);
            e[0][2] = ffma2(a0.x, x2v.x, e[0][2]); e[0][2] = ffma2(a0.y, x2v.y, e[0][2]);
            e[0][3] = ffma2(a0.x, x3.x,  e[0][3]); e[0][3] = ffma2(a0.y, x3.y,  e[0][3]);
            e[1][0] = ffma2(a1.x, x0.x,  e[1][0]); e[1][0] = ffma2(a1.y, x0.y,  e[1][0]);
            e[1][1] = ffma2(a1.x, x1.x,  e[1][1]); e[1][1] = ffma2(a1.y, x1.y,  e[1][1]);
            e[1][2] = ffma2(a1.x, x2v.x, e[1][2]); e[1][2] = ffma2(a1.y, x2v.y, e[1][2]);
            e[1][3] = ffma2(a1.x, x3.x,  e[1][3]); e[1][3] = ffma2(a1.y, x3.y,  e[1][3]);
            e[2][0] = ffma2(a2.x, x0.x,  e[2][0]); e[2][0] = ffma2(a2.y, x0.y,  e[2][0]);
            e[2][1] = ffma2(a2.x, x1.x,  e[2][1]); e[2][1] = ffma2(a2.y, x1.y,  e[2][1]);
            e[2][2] = ffma2(a2.x, x2v.x, e[2][2]); e[2][2] = ffma2(a2.y, x2v.y, e[2][2]);
            e[2][3] = ffma2(a2.x, x3.x,  e[2][3]); e[2][3] = ffma2(a2.y, x3.y,  e[2][3]);
            e[3][0] = ffma2(a3.x, x0.x,  e[3][0]); e[3][0] = ffma2(a3.y, x0.y,  e[3][0]);
            e[3][1] = ffma2(a3.x, x1.x,  e[3][1]); e[3][1] = ffma2(a3.y, x1.y,  e[3][1]);
            e[3][2] = ffma2(a3.x, x2v.x, e[3][2]); e[3][2] = ffma2(a3.y, x2v.y, e[3][2]);
            e[3][3] = ffma2(a3.x, x3.x,  e[3][3]); e[3][3] = ffma2(a3.y, x3.y,  e[3][3]);
            sa[0] = fadd2(sa[0], fadd2(a0.x, a0.y));
            sa[1] = fadd2(sa[1], fadd2(a1.x, a1.y));
            sa[2] = fadd2(sa[2], fadd2(a2.x, a2.y));
            sa[3] = fadd2(sa[3], fadd2(a3.x, a3.y));
        }

        float* E = out + b * (K_ * C_);
        #pragma unroll
        for (int j = 0; j < 4; ++j) {
            #pragma unroll
            for (int cj = 0; cj < 4; ++cj) {
                float2 f = unpack2(e[j][cj]);
                atomicAdd(&E[(k0b + j) * C_ + cg + 16 * cj], f.x + f.y);
            }
        }
        if (cg == 0) {
            #pragma unroll
            for (int j = 0; j < 4; ++j) {
                float2 f = unpack2(sa[j]);
                atomicAdd(&g_asum[b*K_ + k0b + j], f.x + f.y);
            }
        }
    }
}

// ---------------------------------------------------------------------------
__global__ void enc_final(const float* __restrict__ cwg, float* __restrict__ out) {
    int i = blockIdx.x * 256 + threadIdx.x;
    if (i >= E_ELEMS) return;
    int c  = i & 63;
    int bk = i >> 6;
    int k  = bk & 31;
    out[i] -= g_asum[bk] * cwg[k*64 + c];
}

// ---------------------------------------------------------------------------
extern "C" void kernel_launch(void* const* d_in, const int* in_sizes, int n_in,
                              void* d_out, int out_size) {
    const float* X   = (const float*)d_in[0];
    const float* cwg = (const float*)d_in[1];
    const float* scl = (const float*)d_in[2];
    float* out = (float*)d_out;

    // floats: 8448 + 4224 + 4352 + 128 + 32 + 128 = 17312 -> 69,248 B
    const int smem_bytes = (64*XS + 32*LS + 64*CWS2 + 128 + 32 + 128) * 4;
    cudaFuncSetAttribute(enc_main, cudaFuncAttributeMaxDynamicSharedMemorySize,
                         smem_bytes);

    enc_init<<<32, 256>>>(out);
    enc_main<<<4096, 128, smem_bytes>>>(X, cwg, scl, out);
    enc_final<<<32, 256>>>(cwg, out);
}

// round 17
// speedup vs baseline: 1.6453x; 1.6453x over previous
#include <cuda_runtime.h>

#define B_  4
#define C_  64
#define K_  32
#define N_  131072           // D*H*W
#define TN  128              // n-tile per block
#define XS  132              // X tile row stride (words; 528B = 16B-aligned)
#define LS  132              // L/A tile row stride
#define CWS 36               // transposed codeword stride
#define E_ELEMS (B_*K_*C_)   // 8192

__device__ float g_asum[B_*K_];

typedef unsigned long long u64;

__device__ __forceinline__ u64 ffma2(u64 a, u64 b, u64 c) {
    u64 d; asm("fma.rn.f32x2 %0, %1, %2, %3;" : "=l"(d) : "l"(a), "l"(b), "l"(c));
    return d;
}
__device__ __forceinline__ u64 fadd2(u64 a, u64 b) {
    u64 d; asm("add.rn.f32x2 %0, %1, %2;" : "=l"(d) : "l"(a), "l"(b));
    return d;
}
__device__ __forceinline__ float2 unpack2(u64 v) {
    float2 r; asm("mov.b64 {%0, %1}, %2;" : "=f"(r.x), "=f"(r.y) : "l"(v));
    return r;
}
__device__ __forceinline__ unsigned cvt_tf32(float x) {
    unsigned r; asm("cvt.rna.tf32.f32 %0, %1;" : "=r"(r) : "f"(x)); return r;
}
__device__ __forceinline__ void mma_tf32(float* d, const unsigned* a, const unsigned* b) {
    asm volatile("mma.sync.aligned.m16n8k8.row.col.f32.tf32.tf32.f32 "
        "{%0,%1,%2,%3},{%4,%5,%6,%7},{%8,%9},{%0,%1,%2,%3};"
        : "+f"(d[0]), "+f"(d[1]), "+f"(d[2]), "+f"(d[3])
        : "r"(a[0]), "r"(a[1]), "r"(a[2]), "r"(a[3]), "r"(b[0]), "r"(b[1]));
}

// ---------------------------------------------------------------------------
__global__ void enc_init(float* __restrict__ out) {
    int i = blockIdx.x * 256 + threadIdx.x;
    if (i < E_ELEMS) out[i] = 0.0f;
    if (i < B_*K_)   g_asum[i] = 0.0f;
}

// ---------------------------------------------------------------------------
// One block = one (b, 128-n) tile. Grid = 4 * 1024 = 4096 blocks, 128 threads.
// ---------------------------------------------------------------------------
__global__ __launch_bounds__(128, 3) void enc_main(
    const float* __restrict__ X,    // (B, C, N)
    const float* __restrict__ cwg,  // (K, C)
    const float* __restrict__ sclg, // (K,)
    float* __restrict__ out)        // [E | coefA]
{
    extern __shared__ float sm[];
    float* Xs  = sm;                  // 64*132  X tile, [c][n] linear
    float* Lb  = Xs + 64*XS;          // 32*132  dots -> A, [k][n] linear
    float* cwt = Lb + 32*LS;          // 64*36   codewords^T
    float* scl = cwt + 64*CWS;        // 32
    float* c4  = scl + 32;            // 32*4  (scl, -2*scl, scl*c2, 0)

    const int tid = threadIdx.x;
    const int b   = blockIdx.x >> 10;          // /1024
    const int n0  = (blockIdx.x & 1023) << 7;  // *128

    // ---- stage X tile (vectorized, coalesced, linear layout) ----
    const float* Xb = X + (size_t)b * C_ * N_ + n0;
    #pragma unroll
    for (int i = 0; i < 16; ++i) {
        int f = i * 128 + tid;
        int c = f >> 5, q = f & 31;            // 32 float4 per 128-n row
        float4 v = *(const float4*)(Xb + (size_t)c * N_ + q * 4);
        *(float4*)(Xs + c * XS + q * 4) = v;
    }
    // ---- stage codewords transposed [c][k] ----
    #pragma unroll
    for (int i = 0; i < 16; ++i) {
        int f = i * 128 + tid;        // f = k*64 + c
        cwt[(f & 63) * CWS + (f >> 6)] = cwg[f];
    }
    if (tid < K_) scl[tid] = sclg[tid];
    __syncthreads();

    if (tid < K_) {
        float s = 0.f;
        #pragma unroll
        for (int c = 0; c < C_; ++c) { float w = cwt[c*CWS + tid]; s = fmaf(w, w, s); }
        float sc = scl[tid];
        float4 v; v.x = sc; v.y = -2.f * sc; v.z = sc * s; v.w = 0.f;
        *(float4*)(c4 + tid * 4) = v;
    }
    __syncthreads();

    // ---- Phase 1: dots[n,k] via mma.sync tf32. Warp owns 32 n (2 m-tiles).
    //      m = token n, n = codeword k (4 tiles of 8), kdim = channel c (8 steps).
    {
        const int lane = tid & 31, wp = tid >> 5;
        const int g = lane >> 2, tg = lane & 3;
        const int m0 = wp * 32;

        float d[2][4][4];
        #pragma unroll
        for (int mt = 0; mt < 2; ++mt)
            #pragma unroll
            for (int j = 0; j < 4; ++j)
                #pragma unroll
                for (int r = 0; r < 4; ++r) d[mt][j][r] = 0.f;

        #pragma unroll
        for (int s = 0; s < 8; ++s) {
            const float* xc0 = Xs + (8*s + tg) * XS;       // c = 8s+tg
            const float* xc1 = Xs + (8*s + tg + 4) * XS;   // c = 8s+tg+4
            unsigned a[2][4], bv[4][2];
            #pragma unroll
            for (int mt = 0; mt < 2; ++mt) {
                int rn = m0 + mt*16 + g;
                a[mt][0] = cvt_tf32(xc0[rn]);
                a[mt][1] = cvt_tf32(xc0[rn + 8]);
                a[mt][2] = cvt_tf32(xc1[rn]);
                a[mt][3] = cvt_tf32(xc1[rn + 8]);
            }
            const float* w0 = cwt + (8*s + tg) * CWS;
            const float* w1 = cwt + (8*s + tg + 4) * CWS;
            #pragma unroll
            for (int j = 0; j < 4; ++j) {
                bv[j][0] = cvt_tf32(w0[8*j + g]);
                bv[j][1] = cvt_tf32(w1[8*j + g]);
            }
            #pragma unroll
            for (int mt = 0; mt < 2; ++mt)
                #pragma unroll
                for (int j = 0; j < 4; ++j)
                    mma_tf32(d[mt][j], a[mt], bv[j]);
        }
        // store dots into Lb[k][n]
        #pragma unroll
        for (int mt = 0; mt < 2; ++mt) {
            int rn = m0 + mt*16 + g;
            #pragma unroll
            for (int j = 0; j < 4; ++j) {
                int k = 8*j + 2*tg;
                Lb[ k      * LS + rn    ] = d[mt][j][0];
                Lb[(k + 1) * LS + rn    ] = d[mt][j][1];
                Lb[ k      * LS + rn + 8] = d[mt][j][2];
                Lb[(k + 1) * LS + rn + 8] = d[mt][j][3];
            }
        }
    }
    __syncthreads();

    // ---- Softmax per n = tid (0..127): x2 inline, coefA out, A in place ----
    {
        float x2 = 0.f;
        #pragma unroll
        for (int c = 0; c < C_; ++c) {
            float xv = Xs[c * XS + tid];
            x2 = fmaf(xv, xv, x2);
        }
        float lg[K_];
        float mx = -1e30f;
        #pragma unroll
        for (int k = 0; k < K_; ++k) {
            float4 cc = *(const float4*)(c4 + k * 4);
            float d = Lb[k * LS + tid];
            float l = fmaf(cc.y, d, fmaf(cc.x, x2, cc.z));
            lg[k] = l;
            mx = fmaxf(mx, l);
        }
        float s = 0.f;
        #pragma unroll
        for (int k = 0; k < K_; ++k) { float e = __expf(lg[k] - mx); lg[k] = e; s += e; }
        float inv = __fdividef(1.f, s);
        float* coefA = out + E_ELEMS + (size_t)b * K_ * N_ + n0 + tid;
        #pragma unroll
        for (int k = 0; k < K_; ++k) {
            float a = lg[k] * inv;
            coefA[(size_t)k * N_] = a;     // coalesced per k
            Lb[k * LS + tid] = a;          // same words this thread read -> safe
        }
    }
    __syncthreads();

    // ---- Phase 2: A^T X, 4k x 4c per thread, c interleaved (c = cg + 16*cj),
    //      128 n, LINEAR addressing (conflict-free) ----
    {
        const int kg  = tid >> 4;            // 0..7 -> k rows 4kg..4kg+3
        const int cg  = tid & 15;            // c cols: cg, cg+16, cg+32, cg+48
        const int k0b = kg * 4;

        const float* Ar = Lb + k0b * LS;
        const float* Xc = Xs + cg  * XS;

        u64 e[4][4];                         // [k][cj]
        u64 sa[4];
        #pragma unroll
        for (int j = 0; j < 4; ++j) {
            sa[j] = 0ull;
            #pragma unroll
            for (int cj = 0; cj < 4; ++cj) e[j][cj] = 0ull;
        }

        #pragma unroll 2
        for (int n = 0; n < TN; n += 4) {
            ulonglong2 x0 = *(const ulonglong2*)(Xc +  0 * XS + n);
            ulonglong2 x1 = *(const ulonglong2*)(Xc + 16 * XS + n);
            ulonglong2 x2v = *(const ulonglong2*)(Xc + 32 * XS + n);
            ulonglong2 x3 = *(const ulonglong2*)(Xc + 48 * XS + n);
            ulonglong2 a0 = *(const ulonglong2*)(Ar + 0 * LS + n);
            ulonglong2 a1 = *(const ulonglong2*)(Ar + 1 * LS + n);
            ulonglong2 a2 = *(const ulonglong2*)(Ar + 2 * LS + n);
            ulonglong2 a3 = *(const ulonglong2*)(Ar + 3 * LS + n);

            e[0][0] = ffma2(a0.x, x0.x,  e[0][0]); e[0][0] = ffma2(a0.y, x0.y,  e[0][0]);
            e[0][1] = ffma2(a0.x, x1.x,  e[0][1]); e[0][1] = ffma2(a0.y, x1.y,  e[0][1]);
            e[0][2] = ffma2(a0.x, x2v.x, e[0][2]); e[0][2] = ffma2(a0.y, x2v.y, e[0][2]);
            e[0][3] = ffma2(a0.x, x3.x,  e[0][3]); e[0][3] = ffma2(a0.y, x3.y,  e[0][3]);
            e[1][0] = ffma2(a1.x, x0.x,  e[1][0]); e[1][0] = ffma2(a1.y, x0.y,  e[1][0]);
            e[1][1] = ffma2(a1.x, x1.x,  e[1][1]); e[1][1] = ffma2(a1.y, x1.y,  e[1][1]);
            e[1][2] = ffma2(a1.x, x2v.x, e[1][2]); e[1][2] = ffma2(a1.y, x2v.y, e[1][2]);
            e[1][3] = ffma2(a1.x, x3.x,  e[1][3]); e[1][3] = ffma2(a1.y, x3.y,  e[1][3]);
            e[2][0] = ffma2(a2.x, x0.x,  e[2][0]); e[2][0] = ffma2(a2.y, x0.y,  e[2][0]);
            e[2][1] = ffma2(a2.x, x1.x,  e[2][1]); e[2][1] = ffma2(a2.y, x1.y,  e[2][1]);
            e[2][2] = ffma2(a2.x, x2v.x, e[2][2]); e[2][2] = ffma2(a2.y, x2v.y, e[2][2]);
            e[2][3] = ffma2(a2.x, x3.x,  e[2][3]); e[2][3] = ffma2(a2.y, x3.y,  e[2][3]);
            e[3][0] = ffma2(a3.x, x0.x,  e[3][0]); e[3][0] = ffma2(a3.y, x0.y,  e[3][0]);
            e[3][1] = ffma2(a3.x, x1.x,  e[3][1]); e[3][1] = ffma2(a3.y, x1.y,  e[3][1]);
            e[3][2] = ffma2(a3.x, x2v.x, e[3][2]); e[3][2] = ffma2(a3.y, x2v.y, e[3][2]);
            e[3][3] = ffma2(a3.x, x3.x,  e[3][3]); e[3][3] = ffma2(a3.y, x3.y,  e[3][3]);
            sa[0] = fadd2(sa[0], fadd2(a0.x, a0.y));
            sa[1] = fadd2(sa[1], fadd2(a1.x, a1.y));
            sa[2] = fadd2(sa[2], fadd2(a2.x, a2.y));
            sa[3] = fadd2(sa[3], fadd2(a3.x, a3.y));
        }

        float* E = out + b * (K_ * C_);
        #pragma unroll
        for (int j = 0; j < 4; ++j) {
            #pragma unroll
            for (int cj = 0; cj < 4; ++cj) {
                float2 f = unpack2(e[j][cj]);
                atomicAdd(&E[(k0b + j) * C_ + cg + 16 * cj], f.x + f.y);
            }
        }
        if (cg == 0) {
            #pragma unroll
            for (int j = 0; j < 4; ++j) {
                float2 f = unpack2(sa[j]);
                atomicAdd(&g_asum[b*K_ + k0b + j], f.x + f.y);
            }
        }
    }
}

// ---------------------------------------------------------------------------
__global__ void enc_final(const float* __restrict__ cwg, float* __restrict__ out) {
    int i = blockIdx.x * 256 + threadIdx.x;
    if (i >= E_ELEMS) return;
    int c  = i & 63;
    int bk = i >> 6;
    int k  = bk & 31;
    out[i] -= g_asum[bk] * cwg[k*64 + c];
}

// ---------------------------------------------------------------------------
extern "C" void kernel_launch(void* const* d_in, const int* in_sizes, int n_in,
                              void* d_out, int out_size) {
    const float* X   = (const float*)d_in[0];
    const float* cwg = (const float*)d_in[1];
    const float* scl = (const float*)d_in[2];
    float* out = (float*)d_out;

    const int smem_bytes = (64*XS + 32*LS + 64*CWS + 32 + 128) * 4; // 60,544 B
    cudaFuncSetAttribute(enc_main, cudaFuncAttributeMaxDynamicSharedMemorySize,
                         smem_bytes);

    enc_init<<<32, 256>>>(out);
    enc_main<<<4096, 128, smem_bytes>>>(X, cwg, scl, out);
    enc_final<<<32, 256>>>(cwg, out);
}